// round 12
// baseline (speedup 1.0000x reference)
#include <cuda_runtime.h>
#include <cuda_bf16.h>
#include <cstdint>

#define NMAX   50000
#define EMAX   800000
#define FEATN  128
#define POOLW  384   // 3*128
#define NGRAPH 128
#define SCAN_T 1024

// ---------------- scratch (static device globals; no allocation) -------------
__device__ __align__(256) float g_dis [NMAX];
__device__ __align__(256) int   g_cnt [NMAX];
__device__ __align__(256) int   g_fill[NMAX];
__device__ __align__(256) int   g_off [NMAX + 1];
__device__ __align__(256) int   g_gstart[NGRAPH + 1];
__device__ __align__(256) int   g_src [EMAX];
__device__ __align__(256) float g_hs  [NMAX * FEATN];   // dis[r] * (x @ W)
__device__ __align__(256) float g_x1  [NMAX * FEATN];
__device__ __align__(256) float g_x2  [NMAX * FEATN];

// ---------------- prep: counts, scan, fill, dis, graph bounds ----------------
__global__ void zero_kernel(int n) {
    int i = blockIdx.x * blockDim.x + threadIdx.x;
    if (i < n) { g_cnt[i] = 0; g_fill[i] = 0; }
}

// 4 edges per thread (E divisible by 4)
__global__ void count_kernel(const int* __restrict__ ei_col, int E4) {
    int e = blockIdx.x * blockDim.x + threadIdx.x;
    if (e < E4) {
        int4 c = ((const int4*)ei_col)[e];
        atomicAdd(&g_cnt[c.x], 1);
        atomicAdd(&g_cnt[c.y], 1);
        atomicAdd(&g_cnt[c.z], 1);
        atomicAdd(&g_cnt[c.w], 1);
    }
}

__global__ __launch_bounds__(SCAN_T) void scan_kernel(int n) {
    __shared__ int ssum[SCAN_T];
    int tid = threadIdx.x;
    int chunk = (n + SCAN_T - 1) / SCAN_T;
    int lo = tid * chunk;
    int hi = min(lo + chunk, n);
    int s = 0;
    for (int i = lo; i < hi; i++) s += g_cnt[i];
    ssum[tid] = s;
    __syncthreads();
    for (int d = 1; d < SCAN_T; d <<= 1) {
        int v = (tid >= d) ? ssum[tid - d] : 0;
        __syncthreads();
        ssum[tid] += v;
        __syncthreads();
    }
    int base = (tid > 0) ? ssum[tid - 1] : 0;
    for (int i = lo; i < hi; i++) {
        g_off[i] = base;
        g_dis[i] = rsqrtf(1.0f + (float)g_cnt[i]);
        base += g_cnt[i];
    }
    if (tid == SCAN_T - 1) g_off[n] = base;
}

// 4 edges per thread
__global__ void fill_kernel(const int* __restrict__ ei, int E) {
    int e = blockIdx.x * blockDim.x + threadIdx.x;
    int E4 = E >> 2;
    if (e < E4) {
        int4 r = ((const int4*)ei)[e];
        int4 c = ((const int4*)(ei + E))[e];
        g_src[g_off[c.x] + atomicAdd(&g_fill[c.x], 1)] = r.x;
        g_src[g_off[c.y] + atomicAdd(&g_fill[c.y], 1)] = r.y;
        g_src[g_off[c.z] + atomicAdd(&g_fill[c.z], 1)] = r.z;
        g_src[g_off[c.w] + atomicAdd(&g_fill[c.w], 1)] = r.w;
    }
}

// batch is sorted: find contiguous [start, end) per graph
__global__ void gbound_kernel(const int* __restrict__ batch, int N) {
    int i = blockIdx.x * blockDim.x + threadIdx.x;
    if (i >= N) return;
    int b = batch[i];
    if (i == 0) {
        for (int g = 0; g <= b; g++) g_gstart[g] = 0;
    } else {
        int pb = batch[i - 1];
        for (int g = pb + 1; g <= b; g++) g_gstart[g] = i;
    }
    if (i == N - 1) {
        for (int g = b + 1; g <= NGRAPH; g++) g_gstart[g] = N;
    }
}

// ---------------- TF32 tensor-core GEMM: hs = dis * (X @ W) ------------------
// full-K single-stage: whole 128x128 X tile + full 128x128 W in smem via
// cp.async (32 x 16B per thread, max MLP), in-place f2tf convert, then 256
// uninterrupted MMAs. 1 CTA/SM (134 KB smem).
#define XS2 132   // sX row stride (words): banks 4g+t4 conflict-free, 16B-aligned
#define WS2 136   // sW row stride (words): banks 8t4+g conflict-free, 16B-aligned
#define GEMM_SMEM ((128 * XS2 + 128 * WS2) * 4)

__device__ __forceinline__ uint32_t f2tf(float f) {
    uint32_t r;
    asm("cvt.rna.tf32.f32 %0, %1;" : "=r"(r) : "f"(f));
    return r;
}

__device__ __forceinline__ void cp16(uint32_t dst, const void* src, int sz) {
    asm volatile("cp.async.cg.shared.global [%0], [%1], 16, %2;"
                 :: "r"(dst), "l"(src), "r"(sz));
}

__global__ __launch_bounds__(256) void gemm_tf32_kernel(
    int xsel, const float* __restrict__ Xin, const float* __restrict__ W, int N)
{
    const float* X = (xsel == 0) ? Xin : (xsel == 1 ? g_x1 : g_x2);

    extern __shared__ uint32_t smem[];
    uint32_t* sX = smem;               // [128][XS2]
    uint32_t* sW = smem + 128 * XS2;   // [128][WS2]

    int tid  = threadIdx.x;
    int warp = tid >> 5;
    int lane = tid & 31;
    int g    = lane >> 2;
    int t4   = lane & 3;
    int row0 = blockIdx.x * 128;

    uint32_t sX_base = (uint32_t)__cvta_generic_to_shared(sX);
    uint32_t sW_base = (uint32_t)__cvta_generic_to_shared(sW);

    // ---- async load: X rows (zfill OOB), full W ----
    {
        int r  = tid >> 1;                 // 0..127
        int c0 = (tid & 1) * 64;           // 0 or 64
        int gr = row0 + r;
        const float* xsrc = X + (long)((gr < N) ? gr : 0) * FEATN;
        int sz = (gr < N) ? 16 : 0;
        #pragma unroll
        for (int j = 0; j < 16; j++) {
            int c4 = c0 + j * 4;
            cp16(sX_base + (r * XS2 + c4) * 4, xsrc + c4, sz);
        }
        const float* wsrc = W + (long)r * FEATN;
        #pragma unroll
        for (int j = 0; j < 16; j++) {
            int c4 = c0 + j * 4;
            cp16(sW_base + (r * WS2 + c4) * 4, wsrc + c4, 16);
        }
    }
    asm volatile("cp.async.commit_group;");
    asm volatile("cp.async.wait_group 0;");
    __syncthreads();

    // ---- in-place fp32 -> tf32 (keeps rna numerics) ----
    {
        int r  = tid >> 1;
        int c0 = (tid & 1) * 64;
        #pragma unroll
        for (int j = 0; j < 16; j++) {
            int c4 = c0 + j * 4;
            uint32_t* p = &sX[r * XS2 + c4];
            uint4 v = *(uint4*)p;
            v.x = f2tf(__uint_as_float(v.x)); v.y = f2tf(__uint_as_float(v.y));
            v.z = f2tf(__uint_as_float(v.z)); v.w = f2tf(__uint_as_float(v.w));
            *(uint4*)p = v;
            uint32_t* q = &sW[r * WS2 + c4];
            uint4 u = *(uint4*)q;
            u.x = f2tf(__uint_as_float(u.x)); u.y = f2tf(__uint_as_float(u.y));
            u.z = f2tf(__uint_as_float(u.z)); u.w = f2tf(__uint_as_float(u.w));
            *(uint4*)q = u;
        }
    }
    __syncthreads();

    // ---- 256 MMAs, no intermediate syncs ----
    float c[16][4];
    #pragma unroll
    for (int nt = 0; nt < 16; nt++)
        { c[nt][0]=0.f; c[nt][1]=0.f; c[nt][2]=0.f; c[nt][3]=0.f; }

    int ar = warp * 16 + g;
    for (int k8 = 0; k8 < 128; k8 += 8) {
        int ac = k8 + t4;
        uint32_t a0 = sX[ ar      * XS2 + ac    ];
        uint32_t a1 = sX[(ar + 8) * XS2 + ac    ];
        uint32_t a2 = sX[ ar      * XS2 + ac + 4];
        uint32_t a3 = sX[(ar + 8) * XS2 + ac + 4];
        #pragma unroll
        for (int nt = 0; nt < 16; nt++) {
            int bn = nt * 8 + g;
            uint32_t b0 = sW[(k8 + t4    ) * WS2 + bn];
            uint32_t b1 = sW[(k8 + t4 + 4) * WS2 + bn];
            asm volatile(
                "mma.sync.aligned.m16n8k8.row.col.f32.tf32.tf32.f32 "
                "{%0,%1,%2,%3}, {%4,%5,%6,%7}, {%8,%9}, {%0,%1,%2,%3};"
                : "+f"(c[nt][0]), "+f"(c[nt][1]), "+f"(c[nt][2]), "+f"(c[nt][3])
                : "r"(a0), "r"(a1), "r"(a2), "r"(a3), "r"(b0), "r"(b1));
        }
    }

    int r0 = row0 + warp * 16 + g;
    int r1 = r0 + 8;
    float d0 = (r0 < N) ? g_dis[r0] : 0.f;
    float d1 = (r1 < N) ? g_dis[r1] : 0.f;
    #pragma unroll
    for (int nt = 0; nt < 16; nt++) {
        int col = nt * 8 + 2 * t4;
        if (r0 < N) {
            float2 h0 = make_float2(c[nt][0] * d0, c[nt][1] * d0);
            *(float2*)(g_hs + (long)r0 * FEATN + col) = h0;
        }
        if (r1 < N) {
            float2 h1 = make_float2(c[nt][2] * d1, c[nt][3] * d1);
            *(float2*)(g_hs + (long)r1 * FEATN + col) = h1;
        }
    }
}

// ---------------- gather + finalize (fused, atomic-free) ---------------------
__global__ __launch_bounds__(256) void gather_kernel(
    const float* __restrict__ b, int outsel, float* __restrict__ x3out, int N)
{
    long idx = (long)blockIdx.x * blockDim.x + threadIdx.x;
    int i = (int)(idx >> 5);
    if (i >= N) return;
    int lane = (int)(idx & 31);
    int l4 = lane * 4;

    float* xnext = (outsel == 1) ? g_x1 : (outsel == 2 ? g_x2 : x3out);

    float4 accA = *(const float4*)(g_hs + (long)i * FEATN + l4);
    float4 accB = make_float4(0.f, 0.f, 0.f, 0.f);

    int s0 = g_off[i];
    int s1 = g_off[i + 1];
    int k = s0;
    for (; k + 8 <= s1; k += 8) {
        int r0 = g_src[k],   r1 = g_src[k+1], r2 = g_src[k+2], r3 = g_src[k+3];
        int r4 = g_src[k+4], r5 = g_src[k+5], r6 = g_src[k+6], r7 = g_src[k+7];
        float4 v0 = *(const float4*)(g_hs + (long)r0 * FEATN + l4);
        float4 v1 = *(const float4*)(g_hs + (long)r1 * FEATN + l4);
        float4 v2 = *(const float4*)(g_hs + (long)r2 * FEATN + l4);
        float4 v3 = *(const float4*)(g_hs + (long)r3 * FEATN + l4);
        float4 v4 = *(const float4*)(g_hs + (long)r4 * FEATN + l4);
        float4 v5 = *(const float4*)(g_hs + (long)r5 * FEATN + l4);
        float4 v6 = *(const float4*)(g_hs + (long)r6 * FEATN + l4);
        float4 v7 = *(const float4*)(g_hs + (long)r7 * FEATN + l4);
        accA.x += (v0.x + v1.x) + (v2.x + v3.x);
        accA.y += (v0.y + v1.y) + (v2.y + v3.y);
        accA.z += (v0.z + v1.z) + (v2.z + v3.z);
        accA.w += (v0.w + v1.w) + (v2.w + v3.w);
        accB.x += (v4.x + v5.x) + (v6.x + v7.x);
        accB.y += (v4.y + v5.y) + (v6.y + v7.y);
        accB.z += (v4.z + v5.z) + (v6.z + v7.z);
        accB.w += (v4.w + v5.w) + (v6.w + v7.w);
    }
    for (; k + 4 <= s1; k += 4) {
        int r0 = g_src[k], r1 = g_src[k+1], r2 = g_src[k+2], r3 = g_src[k+3];
        float4 v0 = *(const float4*)(g_hs + (long)r0 * FEATN + l4);
        float4 v1 = *(const float4*)(g_hs + (long)r1 * FEATN + l4);
        float4 v2 = *(const float4*)(g_hs + (long)r2 * FEATN + l4);
        float4 v3 = *(const float4*)(g_hs + (long)r3 * FEATN + l4);
        accA.x += (v0.x + v1.x) + (v2.x + v3.x);
        accA.y += (v0.y + v1.y) + (v2.y + v3.y);
        accA.z += (v0.z + v1.z) + (v2.z + v3.z);
        accA.w += (v0.w + v1.w) + (v2.w + v3.w);
    }
    for (; k < s1; k++) {
        int r = g_src[k];
        float4 v = *(const float4*)(g_hs + (long)r * FEATN + l4);
        accB.x += v.x; accB.y += v.y; accB.z += v.z; accB.w += v.w;
    }
    accA.x += accB.x; accA.y += accB.y; accA.z += accB.z; accA.w += accB.w;

    float d = g_dis[i];
    float4 bv = *(const float4*)(b + l4);
    float4 o;
    o.x = fmaxf(accA.x * d + bv.x, 0.f);
    o.y = fmaxf(accA.y * d + bv.y, 0.f);
    o.z = fmaxf(accA.z * d + bv.z, 0.f);
    o.w = fmaxf(accA.w * d + bv.w, 0.f);
    *(float4*)(xnext + (long)i * FEATN + l4) = o;
}

// ---------------- segment-sum pooling (sorted batch, plain stores) -----------
__global__ __launch_bounds__(128) void segpool_kernel(
    int xsel, const float* __restrict__ x3out,
    float* __restrict__ outp, int pool_off)
{
    const float* X = (xsel == 1) ? g_x1 : (xsel == 2 ? g_x2 : x3out);
    int g = blockIdx.x;
    int t = threadIdx.x;
    int s = g_gstart[g];
    int e = g_gstart[g + 1];
    float a0 = 0.f, a1 = 0.f, a2 = 0.f, a3 = 0.f;
    int i = s;
    for (; i + 4 <= e; i += 4) {
        a0 += X[(long)(i    ) * FEATN + t];
        a1 += X[(long)(i + 1) * FEATN + t];
        a2 += X[(long)(i + 2) * FEATN + t];
        a3 += X[(long)(i + 3) * FEATN + t];
    }
    for (; i < e; i++) a0 += X[(long)i * FEATN + t];
    outp[(long)g * POOLW + pool_off + t] = (a0 + a1) + (a2 + a3);
}

// ---------------- launch ------------------------------------------------------
extern "C" void kernel_launch(void* const* d_in, const int* in_sizes, int n_in,
                              void* d_out, int out_size)
{
    const float* x     = (const float*)d_in[0];
    const int*   ei    = (const int*)d_in[1];    // int32 (JAX x64 disabled)
    const int*   batch = (const int*)d_in[2];
    const float* W0    = (const float*)d_in[3];
    const float* b0    = (const float*)d_in[4];
    const float* W1    = (const float*)d_in[5];
    const float* b1    = (const float*)d_in[6];
    const float* W2    = (const float*)d_in[7];
    const float* b2    = (const float*)d_in[8];

    int N = in_sizes[0] / FEATN;     // 50000
    int E = in_sizes[1] / 2;         // 800000
    int pool_elems = NGRAPH * POOLW; // 49152

    float* out = (float*)d_out;
    float* x3  = out + pool_elems;

    cudaFuncSetAttribute(gemm_tf32_kernel,
                         cudaFuncAttributeMaxDynamicSharedMemorySize, GEMM_SMEM);

    // prep: zero, count(x4), scan(+dis), fill(x4), graph bounds
    zero_kernel<<<(N + 255) / 256, 256>>>(N);
    int E4 = E >> 2;
    count_kernel<<<(E4 + 255) / 256, 256>>>(ei + E, E4);
    scan_kernel<<<1, SCAN_T>>>(N);
    fill_kernel<<<(E4 + 255) / 256, 256>>>(ei, E);
    gbound_kernel<<<(N + 255) / 256, 256>>>(batch, N);

    int gemm_blocks  = (N + 127) / 128;
    long gat_threads = (long)N * 32;
    int gat_blocks   = (int)((gat_threads + 255) / 256);

    // layer 1
    gemm_tf32_kernel<<<gemm_blocks, 256, GEMM_SMEM>>>(0, x, W0, N);
    gather_kernel<<<gat_blocks, 256>>>(b0, 1, nullptr, N);
    segpool_kernel<<<NGRAPH, 128>>>(1, nullptr, out, 0);

    // layer 2
    gemm_tf32_kernel<<<gemm_blocks, 256, GEMM_SMEM>>>(1, nullptr, W1, N);
    gather_kernel<<<gat_blocks, 256>>>(b1, 2, nullptr, N);
    segpool_kernel<<<NGRAPH, 128>>>(2, nullptr, out, 128);

    // layer 3
    gemm_tf32_kernel<<<gemm_blocks, 256, GEMM_SMEM>>>(2, nullptr, W2, N);
    gather_kernel<<<gat_blocks, 256>>>(b2, 3, x3, N);
    segpool_kernel<<<NGRAPH, 128>>>(3, x3, out, 256);
}

// round 13
// speedup vs baseline: 1.1453x; 1.1453x over previous
#include <cuda_runtime.h>
#include <cuda_bf16.h>
#include <cstdint>

#define NMAX   50000
#define EMAX   800000
#define FEATN  128
#define POOLW  384   // 3*128
#define NGRAPH 128
#define SCAN_T 1024

// ---------------- scratch (static device globals; no allocation) -------------
__device__ __align__(256) float g_dis [NMAX];
__device__ __align__(256) int   g_cnt [NMAX];
__device__ __align__(256) int   g_fill[NMAX];
__device__ __align__(256) int   g_off [NMAX + 1];
__device__ __align__(256) int   g_gstart[NGRAPH + 1];
__device__ __align__(256) int   g_src [EMAX];
__device__ __align__(256) float g_hs  [NMAX * FEATN];   // dis[r] * (x @ W)
__device__ __align__(256) float g_x1  [NMAX * FEATN];
__device__ __align__(256) float g_x2  [NMAX * FEATN];

// ---------------- prep: counts, scan, fill, dis, graph bounds ----------------
__global__ void zero_kernel(int n) {
    int i = blockIdx.x * blockDim.x + threadIdx.x;
    if (i < n) { g_cnt[i] = 0; g_fill[i] = 0; }
}

__global__ void count_kernel(const int* __restrict__ ei_col, int E) {
    int e = blockIdx.x * blockDim.x + threadIdx.x;
    if (e < E) atomicAdd(&g_cnt[ei_col[e]], 1);
}

__global__ __launch_bounds__(SCAN_T) void scan_kernel(int n) {
    __shared__ int ssum[SCAN_T];
    int tid = threadIdx.x;
    int chunk = (n + SCAN_T - 1) / SCAN_T;
    int lo = tid * chunk;
    int hi = min(lo + chunk, n);
    int s = 0;
    for (int i = lo; i < hi; i++) s += g_cnt[i];
    ssum[tid] = s;
    __syncthreads();
    for (int d = 1; d < SCAN_T; d <<= 1) {
        int v = (tid >= d) ? ssum[tid - d] : 0;
        __syncthreads();
        ssum[tid] += v;
        __syncthreads();
    }
    int base = (tid > 0) ? ssum[tid - 1] : 0;
    for (int i = lo; i < hi; i++) {
        g_off[i] = base;
        g_dis[i] = rsqrtf(1.0f + (float)g_cnt[i]);
        base += g_cnt[i];
    }
    if (tid == SCAN_T - 1) g_off[n] = base;
}

__global__ void fill_kernel(const int* __restrict__ ei, int E) {
    int e = blockIdx.x * blockDim.x + threadIdx.x;
    if (e < E) {
        int c = ei[E + e];
        int pos = g_off[c] + atomicAdd(&g_fill[c], 1);
        g_src[pos] = ei[e];
    }
}

// batch is sorted: find contiguous [start, end) per graph
__global__ void gbound_kernel(const int* __restrict__ batch, int N) {
    int i = blockIdx.x * blockDim.x + threadIdx.x;
    if (i >= N) return;
    int b = batch[i];
    if (i == 0) {
        for (int g = 0; g <= b; g++) g_gstart[g] = 0;
    } else {
        int pb = batch[i - 1];
        for (int g = pb + 1; g <= b; g++) g_gstart[g] = i;
    }
    if (i == N - 1) {
        for (int g = b + 1; g <= NGRAPH; g++) g_gstart[g] = N;
    }
}

// ---------------- TF32 tensor-core GEMM: hs = dis * (X @ W) ------------------
#define XS 36    // sX row stride (floats): conflict-free
#define WS 136   // sW row stride (floats): conflict-free

__device__ __forceinline__ uint32_t f2tf(float f) {
    uint32_t r;
    asm("cvt.rna.tf32.f32 %0, %1;" : "=r"(r) : "f"(f));
    return r;
}

__global__ __launch_bounds__(256) void gemm_tf32_kernel(
    int xsel, const float* __restrict__ Xin, const float* __restrict__ W, int N)
{
    const float* X = (xsel == 0) ? Xin : (xsel == 1 ? g_x1 : g_x2);

    __shared__ uint32_t sX[128 * XS];   // [row][k] tf32
    __shared__ uint32_t sW[32 * WS];    // [k][col] tf32

    int tid  = threadIdx.x;
    int warp = tid >> 5;
    int lane = tid & 31;
    int g    = lane >> 2;
    int t4   = lane & 3;
    int row0 = blockIdx.x * 128;

    float c[16][4];
    #pragma unroll
    for (int nt = 0; nt < 16; nt++)
        { c[nt][0]=0.f; c[nt][1]=0.f; c[nt][2]=0.f; c[nt][3]=0.f; }

    #pragma unroll
    for (int kc = 0; kc < FEATN; kc += 32) {
        #pragma unroll
        for (int i = 0; i < 4; i++) {
            int idx = tid + i * 256;
            int r   = idx >> 3;
            int c4  = (idx & 7) * 4;
            float4 v = make_float4(0.f, 0.f, 0.f, 0.f);
            int gr = row0 + r;
            if (gr < N) v = *(const float4*)(X + (long)gr * FEATN + kc + c4);
            sX[r * XS + c4 + 0] = f2tf(v.x);
            sX[r * XS + c4 + 1] = f2tf(v.y);
            sX[r * XS + c4 + 2] = f2tf(v.z);
            sX[r * XS + c4 + 3] = f2tf(v.w);
        }
        #pragma unroll
        for (int i = 0; i < 4; i++) {
            int idx = tid + i * 256;
            int r   = idx >> 5;
            int c4  = (idx & 31) * 4;
            float4 v = *(const float4*)(W + (long)(kc + r) * FEATN + c4);
            sW[r * WS + c4 + 0] = f2tf(v.x);
            sW[r * WS + c4 + 1] = f2tf(v.y);
            sW[r * WS + c4 + 2] = f2tf(v.z);
            sW[r * WS + c4 + 3] = f2tf(v.w);
        }
        __syncthreads();

        #pragma unroll
        for (int k8 = 0; k8 < 32; k8 += 8) {
            int ar = warp * 16 + g;
            int ac = k8 + t4;
            uint32_t a0 = sX[ ar      * XS + ac    ];
            uint32_t a1 = sX[(ar + 8) * XS + ac    ];
            uint32_t a2 = sX[ ar      * XS + ac + 4];
            uint32_t a3 = sX[(ar + 8) * XS + ac + 4];
            #pragma unroll
            for (int nt = 0; nt < 16; nt++) {
                int bn = nt * 8 + g;
                uint32_t b0 = sW[(k8 + t4    ) * WS + bn];
                uint32_t b1 = sW[(k8 + t4 + 4) * WS + bn];
                asm volatile(
                    "mma.sync.aligned.m16n8k8.row.col.f32.tf32.tf32.f32 "
                    "{%0,%1,%2,%3}, {%4,%5,%6,%7}, {%8,%9}, {%0,%1,%2,%3};"
                    : "+f"(c[nt][0]), "+f"(c[nt][1]), "+f"(c[nt][2]), "+f"(c[nt][3])
                    : "r"(a0), "r"(a1), "r"(a2), "r"(a3), "r"(b0), "r"(b1));
            }
        }
        __syncthreads();
    }

    int r0 = row0 + warp * 16 + g;
    int r1 = r0 + 8;
    float d0 = (r0 < N) ? g_dis[r0] : 0.f;
    float d1 = (r1 < N) ? g_dis[r1] : 0.f;
    #pragma unroll
    for (int nt = 0; nt < 16; nt++) {
        int col = nt * 8 + 2 * t4;
        if (r0 < N) {
            float2 h0 = make_float2(c[nt][0] * d0, c[nt][1] * d0);
            *(float2*)(g_hs + (long)r0 * FEATN + col) = h0;
        }
        if (r1 < N) {
            float2 h1 = make_float2(c[nt][2] * d1, c[nt][3] * d1);
            *(float2*)(g_hs + (long)r1 * FEATN + col) = h1;
        }
    }
}

// ---------------- gather + finalize (fused, atomic-free) ---------------------
__global__ __launch_bounds__(256) void gather_kernel(
    const float* __restrict__ b, int outsel, float* __restrict__ x3out, int N)
{
    long idx = (long)blockIdx.x * blockDim.x + threadIdx.x;
    int i = (int)(idx >> 5);
    if (i >= N) return;
    int lane = (int)(idx & 31);
    int l4 = lane * 4;

    float* xnext = (outsel == 1) ? g_x1 : (outsel == 2 ? g_x2 : x3out);

    float4 accA = *(const float4*)(g_hs + (long)i * FEATN + l4);
    float4 accB = make_float4(0.f, 0.f, 0.f, 0.f);

    int s0 = g_off[i];
    int s1 = g_off[i + 1];
    int k = s0;
    for (; k + 8 <= s1; k += 8) {
        int r0 = g_src[k],   r1 = g_src[k+1], r2 = g_src[k+2], r3 = g_src[k+3];
        int r4 = g_src[k+4], r5 = g_src[k+5], r6 = g_src[k+6], r7 = g_src[k+7];
        float4 v0 = *(const float4*)(g_hs + (long)r0 * FEATN + l4);
        float4 v1 = *(const float4*)(g_hs + (long)r1 * FEATN + l4);
        float4 v2 = *(const float4*)(g_hs + (long)r2 * FEATN + l4);
        float4 v3 = *(const float4*)(g_hs + (long)r3 * FEATN + l4);
        float4 v4 = *(const float4*)(g_hs + (long)r4 * FEATN + l4);
        float4 v5 = *(const float4*)(g_hs + (long)r5 * FEATN + l4);
        float4 v6 = *(const float4*)(g_hs + (long)r6 * FEATN + l4);
        float4 v7 = *(const float4*)(g_hs + (long)r7 * FEATN + l4);
        accA.x += (v0.x + v1.x) + (v2.x + v3.x);
        accA.y += (v0.y + v1.y) + (v2.y + v3.y);
        accA.z += (v0.z + v1.z) + (v2.z + v3.z);
        accA.w += (v0.w + v1.w) + (v2.w + v3.w);
        accB.x += (v4.x + v5.x) + (v6.x + v7.x);
        accB.y += (v4.y + v5.y) + (v6.y + v7.y);
        accB.z += (v4.z + v5.z) + (v6.z + v7.z);
        accB.w += (v4.w + v5.w) + (v6.w + v7.w);
    }
    for (; k + 4 <= s1; k += 4) {
        int r0 = g_src[k], r1 = g_src[k+1], r2 = g_src[k+2], r3 = g_src[k+3];
        float4 v0 = *(const float4*)(g_hs + (long)r0 * FEATN + l4);
        float4 v1 = *(const float4*)(g_hs + (long)r1 * FEATN + l4);
        float4 v2 = *(const float4*)(g_hs + (long)r2 * FEATN + l4);
        float4 v3 = *(const float4*)(g_hs + (long)r3 * FEATN + l4);
        accA.x += (v0.x + v1.x) + (v2.x + v3.x);
        accA.y += (v0.y + v1.y) + (v2.y + v3.y);
        accA.z += (v0.z + v1.z) + (v2.z + v3.z);
        accA.w += (v0.w + v1.w) + (v2.w + v3.w);
    }
    for (; k < s1; k++) {
        int r = g_src[k];
        float4 v = *(const float4*)(g_hs + (long)r * FEATN + l4);
        accB.x += v.x; accB.y += v.y; accB.z += v.z; accB.w += v.w;
    }
    accA.x += accB.x; accA.y += accB.y; accA.z += accB.z; accA.w += accB.w;

    float d = g_dis[i];
    float4 bv = *(const float4*)(b + l4);
    float4 o;
    o.x = fmaxf(accA.x * d + bv.x, 0.f);
    o.y = fmaxf(accA.y * d + bv.y, 0.f);
    o.z = fmaxf(accA.z * d + bv.z, 0.f);
    o.w = fmaxf(accA.w * d + bv.w, 0.f);
    *(float4*)(xnext + (long)i * FEATN + l4) = o;
}

// ---------------- segment-sum pooling (sorted batch, plain stores) -----------
__global__ __launch_bounds__(128) void segpool_kernel(
    int xsel, const float* __restrict__ x3out,
    float* __restrict__ outp, int pool_off)
{
    const float* X = (xsel == 1) ? g_x1 : (xsel == 2 ? g_x2 : x3out);
    int g = blockIdx.x;
    int t = threadIdx.x;
    int s = g_gstart[g];
    int e = g_gstart[g + 1];
    float a0 = 0.f, a1 = 0.f, a2 = 0.f, a3 = 0.f;
    int i = s;
    for (; i + 4 <= e; i += 4) {
        a0 += X[(long)(i    ) * FEATN + t];
        a1 += X[(long)(i + 1) * FEATN + t];
        a2 += X[(long)(i + 2) * FEATN + t];
        a3 += X[(long)(i + 3) * FEATN + t];
    }
    for (; i < e; i++) a0 += X[(long)i * FEATN + t];
    outp[(long)g * POOLW + pool_off + t] = (a0 + a1) + (a2 + a3);
}

// ---------------- launch ------------------------------------------------------
extern "C" void kernel_launch(void* const* d_in, const int* in_sizes, int n_in,
                              void* d_out, int out_size)
{
    const float* x     = (const float*)d_in[0];
    const int*   ei    = (const int*)d_in[1];    // int32 (JAX x64 disabled)
    const int*   batch = (const int*)d_in[2];
    const float* W0    = (const float*)d_in[3];
    const float* b0    = (const float*)d_in[4];
    const float* W1    = (const float*)d_in[5];
    const float* b1    = (const float*)d_in[6];
    const float* W2    = (const float*)d_in[7];
    const float* b2    = (const float*)d_in[8];

    int N = in_sizes[0] / FEATN;     // 50000
    int E = in_sizes[1] / 2;         // 800000
    int pool_elems = NGRAPH * POOLW; // 49152

    float* out = (float*)d_out;
    float* x3  = out + pool_elems;

    int gemm_blocks  = (N + 127) / 128;
    long gat_threads = (long)N * 32;
    int gat_blocks   = (int)((gat_threads + 255) / 256);

    // prep (reordered: gemm1 moved to 4th launch so ncu's capture slot
    // profiles the GEMM; gemm only needs scan's g_dis, not fill/gbound)
    zero_kernel<<<(N + 255) / 256, 256>>>(N);                 // 1
    count_kernel<<<(E + 255) / 256, 256>>>(ei + E, E);        // 2
    scan_kernel<<<1, SCAN_T>>>(N);                            // 3
    gemm_tf32_kernel<<<gemm_blocks, 256>>>(0, x, W0, N);      // 4  <- profiled
    fill_kernel<<<(E + 255) / 256, 256>>>(ei, E);             // 5
    gbound_kernel<<<(N + 255) / 256, 256>>>(batch, N);        // 6

    // layer 1 (gemm already issued above)
    gather_kernel<<<gat_blocks, 256>>>(b0, 1, nullptr, N);
    segpool_kernel<<<NGRAPH, 128>>>(1, nullptr, out, 0);

    // layer 2
    gemm_tf32_kernel<<<gemm_blocks, 256>>>(1, nullptr, W1, N);
    gather_kernel<<<gat_blocks, 256>>>(b1, 2, nullptr, N);
    segpool_kernel<<<NGRAPH, 128>>>(2, nullptr, out, 128);

    // layer 3
    gemm_tf32_kernel<<<gemm_blocks, 256>>>(2, nullptr, W2, N);
    gather_kernel<<<gat_blocks, 256>>>(b2, 3, x3, N);
    segpool_kernel<<<NGRAPH, 128>>>(3, x3, out, 256);
}

// round 15
// speedup vs baseline: 1.1579x; 1.0110x over previous
#include <cuda_runtime.h>
#include <cuda_bf16.h>
#include <cstdint>

#define NMAX   50000
#define EMAX   800000
#define FEATN  128
#define POOLW  384   // 3*128
#define NGRAPH 128
#define SCAN_T 1024

// ---------------- scratch (static device globals; no allocation) -------------
__device__ __align__(256) float g_dis [NMAX];
__device__ __align__(256) int   g_cnt [NMAX];
__device__ __align__(256) int   g_fill[NMAX];
__device__ __align__(256) int   g_off [NMAX + 1];
__device__ __align__(256) int   g_gstart[NGRAPH + 1];
__device__ __align__(256) int   g_src [EMAX];
__device__ __align__(256) float g_hs  [NMAX * FEATN];   // dis[r] * (x @ W)
__device__ __align__(256) float g_x1  [NMAX * FEATN];
__device__ __align__(256) float g_x2  [NMAX * FEATN];

// ---------------- prep: counts, scan, fill, dis, graph bounds ----------------
__global__ void zero_kernel(int n) {
    int i = blockIdx.x * blockDim.x + threadIdx.x;
    if (i < n) { g_cnt[i] = 0; g_fill[i] = 0; }
}

__global__ void count_kernel(const int* __restrict__ ei_col, int E) {
    int e = blockIdx.x * blockDim.x + threadIdx.x;
    if (e < E) atomicAdd(&g_cnt[ei_col[e]], 1);
}

__global__ __launch_bounds__(SCAN_T) void scan_kernel(int n) {
    __shared__ int ssum[SCAN_T];
    int tid = threadIdx.x;
    int chunk = (n + SCAN_T - 1) / SCAN_T;
    int lo = tid * chunk;
    int hi = min(lo + chunk, n);
    int s = 0;
    for (int i = lo; i < hi; i++) s += g_cnt[i];
    ssum[tid] = s;
    __syncthreads();
    for (int d = 1; d < SCAN_T; d <<= 1) {
        int v = (tid >= d) ? ssum[tid - d] : 0;
        __syncthreads();
        ssum[tid] += v;
        __syncthreads();
    }
    int base = (tid > 0) ? ssum[tid - 1] : 0;
    for (int i = lo; i < hi; i++) {
        g_off[i] = base;
        g_dis[i] = rsqrtf(1.0f + (float)g_cnt[i]);
        base += g_cnt[i];
    }
    if (tid == SCAN_T - 1) g_off[n] = base;
}

__global__ void fill_kernel(const int* __restrict__ ei, int E) {
    int e = blockIdx.x * blockDim.x + threadIdx.x;
    if (e < E) {
        int c = ei[E + e];
        int pos = g_off[c] + atomicAdd(&g_fill[c], 1);
        g_src[pos] = ei[e];
    }
}

// batch is sorted: find contiguous [start, end) per graph
__global__ void gbound_kernel(const int* __restrict__ batch, int N) {
    int i = blockIdx.x * blockDim.x + threadIdx.x;
    if (i >= N) return;
    int b = batch[i];
    if (i == 0) {
        for (int g = 0; g <= b; g++) g_gstart[g] = 0;
    } else {
        int pb = batch[i - 1];
        for (int g = pb + 1; g <= b; g++) g_gstart[g] = i;
    }
    if (i == N - 1) {
        for (int g = b + 1; g <= NGRAPH; g++) g_gstart[g] = N;
    }
}

// ---------------- TF32 tensor-core GEMM: hs = dis * (X @ W) ------------------
// 512 threads (16 warps), block tile 128x128, warp = 16 rows x 64 cols
// (8 n-tiles) -> 32 accum regs/thread -> 2x occupancy vs R13.
#define XS 36    // sX row stride (words): conflict-free
#define WS 136   // sW row stride (words): conflict-free

__device__ __forceinline__ uint32_t f2tf(float f) {
    uint32_t r;
    asm("cvt.rna.tf32.f32 %0, %1;" : "=r"(r) : "f"(f));
    return r;
}

__global__ __launch_bounds__(512) void gemm_tf32_kernel(
    int xsel, const float* __restrict__ Xin, const float* __restrict__ W, int N)
{
    const float* X = (xsel == 0) ? Xin : (xsel == 1 ? g_x1 : g_x2);

    __shared__ uint32_t sX[128 * XS];   // [row][k] tf32
    __shared__ uint32_t sW[32 * WS];    // [k][col] tf32

    int tid  = threadIdx.x;
    int warp = tid >> 5;
    int lane = tid & 31;
    int g    = lane >> 2;
    int t4   = lane & 3;
    int wr   = warp >> 1;     // row group 0..7 -> rows wr*16..+16
    int wc   = warp & 1;      // col half 0..1  -> cols wc*64..+64
    int row0 = blockIdx.x * 128;

    float c[8][4];
    #pragma unroll
    for (int nt = 0; nt < 8; nt++)
        { c[nt][0]=0.f; c[nt][1]=0.f; c[nt][2]=0.f; c[nt][3]=0.f; }

    #pragma unroll
    for (int kc = 0; kc < FEATN; kc += 32) {
        // stage X chunk 128x32 (1024 float4, 2/thread), convert to tf32
        #pragma unroll
        for (int i = 0; i < 2; i++) {
            int idx = tid + i * 512;
            int r   = idx >> 3;
            int c4  = (idx & 7) * 4;
            float4 v = make_float4(0.f, 0.f, 0.f, 0.f);
            int gr = row0 + r;
            if (gr < N) v = *(const float4*)(X + (long)gr * FEATN + kc + c4);
            sX[r * XS + c4 + 0] = f2tf(v.x);
            sX[r * XS + c4 + 1] = f2tf(v.y);
            sX[r * XS + c4 + 2] = f2tf(v.z);
            sX[r * XS + c4 + 3] = f2tf(v.w);
        }
        // stage W chunk 32x128 (1024 float4, 2/thread)
        #pragma unroll
        for (int i = 0; i < 2; i++) {
            int idx = tid + i * 512;
            int r   = idx >> 5;
            int c4  = (idx & 31) * 4;
            float4 v = *(const float4*)(W + (long)(kc + r) * FEATN + c4);
            sW[r * WS + c4 + 0] = f2tf(v.x);
            sW[r * WS + c4 + 1] = f2tf(v.y);
            sW[r * WS + c4 + 2] = f2tf(v.z);
            sW[r * WS + c4 + 3] = f2tf(v.w);
        }
        __syncthreads();

        #pragma unroll
        for (int k8 = 0; k8 < 32; k8 += 8) {
            int ar = wr * 16 + g;
            int ac = k8 + t4;
            uint32_t a0 = sX[ ar      * XS + ac    ];
            uint32_t a1 = sX[(ar + 8) * XS + ac    ];
            uint32_t a2 = sX[ ar      * XS + ac + 4];
            uint32_t a3 = sX[(ar + 8) * XS + ac + 4];
            #pragma unroll
            for (int nt = 0; nt < 8; nt++) {
                int bn = wc * 64 + nt * 8 + g;
                uint32_t b0 = sW[(k8 + t4    ) * WS + bn];
                uint32_t b1 = sW[(k8 + t4 + 4) * WS + bn];
                asm volatile(
                    "mma.sync.aligned.m16n8k8.row.col.f32.tf32.tf32.f32 "
                    "{%0,%1,%2,%3}, {%4,%5,%6,%7}, {%8,%9}, {%0,%1,%2,%3};"
                    : "+f"(c[nt][0]), "+f"(c[nt][1]), "+f"(c[nt][2]), "+f"(c[nt][3])
                    : "r"(a0), "r"(a1), "r"(a2), "r"(a3), "r"(b0), "r"(b1));
            }
        }
        __syncthreads();
    }

    int r0 = row0 + wr * 16 + g;
    int r1 = r0 + 8;
    float d0 = (r0 < N) ? g_dis[r0] : 0.f;
    float d1 = (r1 < N) ? g_dis[r1] : 0.f;
    #pragma unroll
    for (int nt = 0; nt < 8; nt++) {
        int col = wc * 64 + nt * 8 + 2 * t4;
        if (r0 < N) {
            float2 h0 = make_float2(c[nt][0] * d0, c[nt][1] * d0);
            *(float2*)(g_hs + (long)r0 * FEATN + col) = h0;
        }
        if (r1 < N) {
            float2 h1 = make_float2(c[nt][2] * d1, c[nt][3] * d1);
            *(float2*)(g_hs + (long)r1 * FEATN + col) = h1;
        }
    }
}

// ---------------- gather + finalize (fused, atomic-free) ---------------------
__global__ __launch_bounds__(256) void gather_kernel(
    const float* __restrict__ b, int outsel, float* __restrict__ x3out, int N)
{
    long idx = (long)blockIdx.x * blockDim.x + threadIdx.x;
    int i = (int)(idx >> 5);
    if (i >= N) return;
    int lane = (int)(idx & 31);
    int l4 = lane * 4;

    float* xnext = (outsel == 1) ? g_x1 : (outsel == 2 ? g_x2 : x3out);

    float4 accA = *(const float4*)(g_hs + (long)i * FEATN + l4);
    float4 accB = make_float4(0.f, 0.f, 0.f, 0.f);

    int s0 = g_off[i];
    int s1 = g_off[i + 1];
    int k = s0;
    for (; k + 8 <= s1; k += 8) {
        int r0 = g_src[k],   r1 = g_src[k+1], r2 = g_src[k+2], r3 = g_src[k+3];
        int r4 = g_src[k+4], r5 = g_src[k+5], r6 = g_src[k+6], r7 = g_src[k+7];
        float4 v0 = *(const float4*)(g_hs + (long)r0 * FEATN + l4);
        float4 v1 = *(const float4*)(g_hs + (long)r1 * FEATN + l4);
        float4 v2 = *(const float4*)(g_hs + (long)r2 * FEATN + l4);
        float4 v3 = *(const float4*)(g_hs + (long)r3 * FEATN + l4);
        float4 v4 = *(const float4*)(g_hs + (long)r4 * FEATN + l4);
        float4 v5 = *(const float4*)(g_hs + (long)r5 * FEATN + l4);
        float4 v6 = *(const float4*)(g_hs + (long)r6 * FEATN + l4);
        float4 v7 = *(const float4*)(g_hs + (long)r7 * FEATN + l4);
        accA.x += (v0.x + v1.x) + (v2.x + v3.x);
        accA.y += (v0.y + v1.y) + (v2.y + v3.y);
        accA.z += (v0.z + v1.z) + (v2.z + v3.z);
        accA.w += (v0.w + v1.w) + (v2.w + v3.w);
        accB.x += (v4.x + v5.x) + (v6.x + v7.x);
        accB.y += (v4.y + v5.y) + (v6.y + v7.y);
        accB.z += (v4.z + v5.z) + (v6.z + v7.z);
        accB.w += (v4.w + v5.w) + (v6.w + v7.w);
    }
    for (; k + 4 <= s1; k += 4) {
        int r0 = g_src[k], r1 = g_src[k+1], r2 = g_src[k+2], r3 = g_src[k+3];
        float4 v0 = *(const float4*)(g_hs + (long)r0 * FEATN + l4);
        float4 v1 = *(const float4*)(g_hs + (long)r1 * FEATN + l4);
        float4 v2 = *(const float4*)(g_hs + (long)r2 * FEATN + l4);
        float4 v3 = *(const float4*)(g_hs + (long)r3 * FEATN + l4);
        accA.x += (v0.x + v1.x) + (v2.x + v3.x);
        accA.y += (v0.y + v1.y) + (v2.y + v3.y);
        accA.z += (v0.z + v1.z) + (v2.z + v3.z);
        accA.w += (v0.w + v1.w) + (v2.w + v3.w);
    }
    for (; k < s1; k++) {
        int r = g_src[k];
        float4 v = *(const float4*)(g_hs + (long)r * FEATN + l4);
        accB.x += v.x; accB.y += v.y; accB.z += v.z; accB.w += v.w;
    }
    accA.x += accB.x; accA.y += accB.y; accA.z += accB.z; accA.w += accB.w;

    float d = g_dis[i];
    float4 bv = *(const float4*)(b + l4);
    float4 o;
    o.x = fmaxf(accA.x * d + bv.x, 0.f);
    o.y = fmaxf(accA.y * d + bv.y, 0.f);
    o.z = fmaxf(accA.z * d + bv.z, 0.f);
    o.w = fmaxf(accA.w * d + bv.w, 0.f);
    *(float4*)(xnext + (long)i * FEATN + l4) = o;
}

// ---------------- segment-sum pooling (sorted batch, plain stores) -----------
__global__ __launch_bounds__(128) void segpool_kernel(
    int xsel, const float* __restrict__ x3out,
    float* __restrict__ outp, int pool_off)
{
    const float* X = (xsel == 1) ? g_x1 : (xsel == 2 ? g_x2 : x3out);
    int g = blockIdx.x;
    int t = threadIdx.x;
    int s = g_gstart[g];
    int e = g_gstart[g + 1];
    float a0 = 0.f, a1 = 0.f, a2 = 0.f, a3 = 0.f;
    int i = s;
    for (; i + 4 <= e; i += 4) {
        a0 += X[(long)(i    ) * FEATN + t];
        a1 += X[(long)(i + 1) * FEATN + t];
        a2 += X[(long)(i + 2) * FEATN + t];
        a3 += X[(long)(i + 3) * FEATN + t];
    }
    for (; i < e; i++) a0 += X[(long)i * FEATN + t];
    outp[(long)g * POOLW + pool_off + t] = (a0 + a1) + (a2 + a3);
}

// ---------------- launch ------------------------------------------------------
extern "C" void kernel_launch(void* const* d_in, const int* in_sizes, int n_in,
                              void* d_out, int out_size)
{
    const float* x     = (const float*)d_in[0];
    const int*   ei    = (const int*)d_in[1];    // int32 (JAX x64 disabled)
    const int*   batch = (const int*)d_in[2];
    const float* W0    = (const float*)d_in[3];
    const float* b0    = (const float*)d_in[4];
    const float* W1    = (const float*)d_in[5];
    const float* b1    = (const float*)d_in[6];
    const float* W2    = (const float*)d_in[7];
    const float* b2    = (const float*)d_in[8];

    int N = in_sizes[0] / FEATN;     // 50000
    int E = in_sizes[1] / 2;         // 800000
    int pool_elems = NGRAPH * POOLW; // 49152

    float* out = (float*)d_out;
    float* x3  = out + pool_elems;

    int gemm_blocks  = (N + 127) / 128;
    long gat_threads = (long)N * 32;
    int gat_blocks   = (int)((gat_threads + 255) / 256);

    // prep (gemm1 in slot 4 = ncu's capture slot)
    zero_kernel<<<(N + 255) / 256, 256>>>(N);                 // 1
    count_kernel<<<(E + 255) / 256, 256>>>(ei + E, E);        // 2
    scan_kernel<<<1, SCAN_T>>>(N);                            // 3
    gemm_tf32_kernel<<<gemm_blocks, 512>>>(0, x, W0, N);      // 4  <- profiled
    fill_kernel<<<(E + 255) / 256, 256>>>(ei, E);             // 5
    gbound_kernel<<<(N + 255) / 256, 256>>>(batch, N);        // 6

    // layer 1 (gemm already issued above)
    gather_kernel<<<gat_blocks, 256>>>(b0, 1, nullptr, N);
    segpool_kernel<<<NGRAPH, 128>>>(1, nullptr, out, 0);

    // layer 2
    gemm_tf32_kernel<<<gemm_blocks, 512>>>(1, nullptr, W1, N);
    gather_kernel<<<gat_blocks, 256>>>(b1, 2, nullptr, N);
    segpool_kernel<<<NGRAPH, 128>>>(2, nullptr, out, 128);

    // layer 3
    gemm_tf32_kernel<<<gemm_blocks, 512>>>(2, nullptr, W2, N);
    gather_kernel<<<gat_blocks, 256>>>(b2, 3, x3, N);
    segpool_kernel<<<NGRAPH, 128>>>(3, x3, out, 256);
}

// round 16
// speedup vs baseline: 1.2345x; 1.0661x over previous
#include <cuda_runtime.h>
#include <cuda_fp16.h>
#include <cstdint>

#define NMAX   50000
#define EMAX   800000
#define FEATN  128
#define POOLW  384   // 3*128
#define NGRAPH 128
#define SCAN_T 1024

// ---------------- scratch (static device globals; no allocation) -------------
__device__ __align__(256) float  g_dis [NMAX];
__device__ __align__(256) int    g_cnt [NMAX];
__device__ __align__(256) int    g_fill[NMAX];
__device__ __align__(256) int    g_off [NMAX + 1];
__device__ __align__(256) int    g_gstart[NGRAPH + 1];
__device__ __align__(256) int    g_src [EMAX];
__device__ __align__(256) __half g_hs  [NMAX * FEATN];  // fp16: dis[r]*(x@W)
__device__ __align__(256) float  g_x1  [NMAX * FEATN];
__device__ __align__(256) float  g_x2  [NMAX * FEATN];

// ---------------- prep: counts, scan, fill, dis, graph bounds ----------------
__global__ void zero_kernel(int n) {
    int i = blockIdx.x * blockDim.x + threadIdx.x;
    if (i < n) { g_cnt[i] = 0; g_fill[i] = 0; }
}

__global__ void count_kernel(const int* __restrict__ ei_col, int E) {
    int e = blockIdx.x * blockDim.x + threadIdx.x;
    if (e < E) atomicAdd(&g_cnt[ei_col[e]], 1);
}

__global__ __launch_bounds__(SCAN_T) void scan_kernel(int n) {
    __shared__ int ssum[SCAN_T];
    int tid = threadIdx.x;
    int chunk = (n + SCAN_T - 1) / SCAN_T;
    int lo = tid * chunk;
    int hi = min(lo + chunk, n);
    int s = 0;
    for (int i = lo; i < hi; i++) s += g_cnt[i];
    ssum[tid] = s;
    __syncthreads();
    for (int d = 1; d < SCAN_T; d <<= 1) {
        int v = (tid >= d) ? ssum[tid - d] : 0;
        __syncthreads();
        ssum[tid] += v;
        __syncthreads();
    }
    int base = (tid > 0) ? ssum[tid - 1] : 0;
    for (int i = lo; i < hi; i++) {
        g_off[i] = base;
        g_dis[i] = rsqrtf(1.0f + (float)g_cnt[i]);
        base += g_cnt[i];
    }
    if (tid == SCAN_T - 1) g_off[n] = base;
}

__global__ void fill_kernel(const int* __restrict__ ei, int E) {
    int e = blockIdx.x * blockDim.x + threadIdx.x;
    if (e < E) {
        int c = ei[E + e];
        int pos = g_off[c] + atomicAdd(&g_fill[c], 1);
        g_src[pos] = ei[e];
    }
}

// batch is sorted: find contiguous [start, end) per graph
__global__ void gbound_kernel(const int* __restrict__ batch, int N) {
    int i = blockIdx.x * blockDim.x + threadIdx.x;
    if (i >= N) return;
    int b = batch[i];
    if (i == 0) {
        for (int g = 0; g <= b; g++) g_gstart[g] = 0;
    } else {
        int pb = batch[i - 1];
        for (int g = pb + 1; g <= b; g++) g_gstart[g] = i;
    }
    if (i == N - 1) {
        for (int g = b + 1; g <= NGRAPH; g++) g_gstart[g] = N;
    }
}

// ---------------- TF32 tensor-core GEMM: hs = dis * (X @ W) ------------------
// 512 threads (16 warps), block tile 128x128, warp = 16 rows x 64 cols.
#define XS 36    // sX row stride (words): conflict-free
#define WS 136   // sW row stride (words): conflict-free

__device__ __forceinline__ uint32_t f2tf(float f) {
    uint32_t r;
    asm("cvt.rna.tf32.f32 %0, %1;" : "=r"(r) : "f"(f));
    return r;
}

__global__ __launch_bounds__(512) void gemm_tf32_kernel(
    int xsel, const float* __restrict__ Xin, const float* __restrict__ W, int N)
{
    const float* X = (xsel == 0) ? Xin : (xsel == 1 ? g_x1 : g_x2);

    __shared__ uint32_t sX[128 * XS];   // [row][k] tf32
    __shared__ uint32_t sW[32 * WS];    // [k][col] tf32

    int tid  = threadIdx.x;
    int warp = tid >> 5;
    int lane = tid & 31;
    int g    = lane >> 2;
    int t4   = lane & 3;
    int wr   = warp >> 1;     // row group 0..7 -> rows wr*16..+16
    int wc   = warp & 1;      // col half 0..1  -> cols wc*64..+64
    int row0 = blockIdx.x * 128;

    float c[8][4];
    #pragma unroll
    for (int nt = 0; nt < 8; nt++)
        { c[nt][0]=0.f; c[nt][1]=0.f; c[nt][2]=0.f; c[nt][3]=0.f; }

    #pragma unroll
    for (int kc = 0; kc < FEATN; kc += 32) {
        #pragma unroll
        for (int i = 0; i < 2; i++) {
            int idx = tid + i * 512;
            int r   = idx >> 3;
            int c4  = (idx & 7) * 4;
            float4 v = make_float4(0.f, 0.f, 0.f, 0.f);
            int gr = row0 + r;
            if (gr < N) v = *(const float4*)(X + (long)gr * FEATN + kc + c4);
            sX[r * XS + c4 + 0] = f2tf(v.x);
            sX[r * XS + c4 + 1] = f2tf(v.y);
            sX[r * XS + c4 + 2] = f2tf(v.z);
            sX[r * XS + c4 + 3] = f2tf(v.w);
        }
        #pragma unroll
        for (int i = 0; i < 2; i++) {
            int idx = tid + i * 512;
            int r   = idx >> 5;
            int c4  = (idx & 31) * 4;
            float4 v = *(const float4*)(W + (long)(kc + r) * FEATN + c4);
            sW[r * WS + c4 + 0] = f2tf(v.x);
            sW[r * WS + c4 + 1] = f2tf(v.y);
            sW[r * WS + c4 + 2] = f2tf(v.z);
            sW[r * WS + c4 + 3] = f2tf(v.w);
        }
        __syncthreads();

        #pragma unroll
        for (int k8 = 0; k8 < 32; k8 += 8) {
            int ar = wr * 16 + g;
            int ac = k8 + t4;
            uint32_t a0 = sX[ ar      * XS + ac    ];
            uint32_t a1 = sX[(ar + 8) * XS + ac    ];
            uint32_t a2 = sX[ ar      * XS + ac + 4];
            uint32_t a3 = sX[(ar + 8) * XS + ac + 4];
            #pragma unroll
            for (int nt = 0; nt < 8; nt++) {
                int bn = wc * 64 + nt * 8 + g;
                uint32_t b0 = sW[(k8 + t4    ) * WS + bn];
                uint32_t b1 = sW[(k8 + t4 + 4) * WS + bn];
                asm volatile(
                    "mma.sync.aligned.m16n8k8.row.col.f32.tf32.tf32.f32 "
                    "{%0,%1,%2,%3}, {%4,%5,%6,%7}, {%8,%9}, {%0,%1,%2,%3};"
                    : "+f"(c[nt][0]), "+f"(c[nt][1]), "+f"(c[nt][2]), "+f"(c[nt][3])
                    : "r"(a0), "r"(a1), "r"(a2), "r"(a3), "r"(b0), "r"(b1));
            }
        }
        __syncthreads();
    }

    // epilogue: hs = fp16(dis * acc)
    int r0 = row0 + wr * 16 + g;
    int r1 = r0 + 8;
    float d0 = (r0 < N) ? g_dis[r0] : 0.f;
    float d1 = (r1 < N) ? g_dis[r1] : 0.f;
    #pragma unroll
    for (int nt = 0; nt < 8; nt++) {
        int col = wc * 64 + nt * 8 + 2 * t4;
        if (r0 < N) {
            __half2 h0 = __floats2half2_rn(c[nt][0] * d0, c[nt][1] * d0);
            *(__half2*)(g_hs + (long)r0 * FEATN + col) = h0;
        }
        if (r1 < N) {
            __half2 h1 = __floats2half2_rn(c[nt][2] * d1, c[nt][3] * d1);
            *(__half2*)(g_hs + (long)r1 * FEATN + col) = h1;
        }
    }
}

// ---------------- gather + finalize (fused, atomic-free, fp16 hs) ------------
__device__ __forceinline__ float4 ldh4(const __half* p) {
    uint2 u = *(const uint2*)p;
    float2 f0 = __half22float2(*(__half2*)&u.x);
    float2 f1 = __half22float2(*(__half2*)&u.y);
    return make_float4(f0.x, f0.y, f1.x, f1.y);
}

__global__ __launch_bounds__(256) void gather_kernel(
    const float* __restrict__ b, int outsel, float* __restrict__ x3out, int N)
{
    long idx = (long)blockIdx.x * blockDim.x + threadIdx.x;
    int i = (int)(idx >> 5);
    if (i >= N) return;
    int lane = (int)(idx & 31);
    int l4 = lane * 4;

    float* xnext = (outsel == 1) ? g_x1 : (outsel == 2 ? g_x2 : x3out);

    float4 accA = ldh4(g_hs + (long)i * FEATN + l4);   // self loop term
    float4 accB = make_float4(0.f, 0.f, 0.f, 0.f);

    int s0 = g_off[i];
    int s1 = g_off[i + 1];
    int k = s0;
    for (; k + 8 <= s1; k += 8) {
        int r0 = g_src[k],   r1 = g_src[k+1], r2 = g_src[k+2], r3 = g_src[k+3];
        int r4 = g_src[k+4], r5 = g_src[k+5], r6 = g_src[k+6], r7 = g_src[k+7];
        float4 v0 = ldh4(g_hs + (long)r0 * FEATN + l4);
        float4 v1 = ldh4(g_hs + (long)r1 * FEATN + l4);
        float4 v2 = ldh4(g_hs + (long)r2 * FEATN + l4);
        float4 v3 = ldh4(g_hs + (long)r3 * FEATN + l4);
        float4 v4 = ldh4(g_hs + (long)r4 * FEATN + l4);
        float4 v5 = ldh4(g_hs + (long)r5 * FEATN + l4);
        float4 v6 = ldh4(g_hs + (long)r6 * FEATN + l4);
        float4 v7 = ldh4(g_hs + (long)r7 * FEATN + l4);
        accA.x += (v0.x + v1.x) + (v2.x + v3.x);
        accA.y += (v0.y + v1.y) + (v2.y + v3.y);
        accA.z += (v0.z + v1.z) + (v2.z + v3.z);
        accA.w += (v0.w + v1.w) + (v2.w + v3.w);
        accB.x += (v4.x + v5.x) + (v6.x + v7.x);
        accB.y += (v4.y + v5.y) + (v6.y + v7.y);
        accB.z += (v4.z + v5.z) + (v6.z + v7.z);
        accB.w += (v4.w + v5.w) + (v6.w + v7.w);
    }
    for (; k + 4 <= s1; k += 4) {
        int r0 = g_src[k], r1 = g_src[k+1], r2 = g_src[k+2], r3 = g_src[k+3];
        float4 v0 = ldh4(g_hs + (long)r0 * FEATN + l4);
        float4 v1 = ldh4(g_hs + (long)r1 * FEATN + l4);
        float4 v2 = ldh4(g_hs + (long)r2 * FEATN + l4);
        float4 v3 = ldh4(g_hs + (long)r3 * FEATN + l4);
        accA.x += (v0.x + v1.x) + (v2.x + v3.x);
        accA.y += (v0.y + v1.y) + (v2.y + v3.y);
        accA.z += (v0.z + v1.z) + (v2.z + v3.z);
        accA.w += (v0.w + v1.w) + (v2.w + v3.w);
    }
    for (; k < s1; k++) {
        int r = g_src[k];
        float4 v = ldh4(g_hs + (long)r * FEATN + l4);
        accB.x += v.x; accB.y += v.y; accB.z += v.z; accB.w += v.w;
    }
    accA.x += accB.x; accA.y += accB.y; accA.z += accB.z; accA.w += accB.w;

    float d = g_dis[i];
    float4 bv = *(const float4*)(b + l4);
    float4 o;
    o.x = fmaxf(accA.x * d + bv.x, 0.f);
    o.y = fmaxf(accA.y * d + bv.y, 0.f);
    o.z = fmaxf(accA.z * d + bv.z, 0.f);
    o.w = fmaxf(accA.w * d + bv.w, 0.f);
    *(float4*)(xnext + (long)i * FEATN + l4) = o;
}

// ---------------- segment-sum pooling (sorted batch, plain stores) -----------
__global__ __launch_bounds__(128) void segpool_kernel(
    int xsel, const float* __restrict__ x3out,
    float* __restrict__ outp, int pool_off)
{
    const float* X = (xsel == 1) ? g_x1 : (xsel == 2 ? g_x2 : x3out);
    int g = blockIdx.x;
    int t = threadIdx.x;
    int s = g_gstart[g];
    int e = g_gstart[g + 1];
    float a0 = 0.f, a1 = 0.f, a2 = 0.f, a3 = 0.f;
    int i = s;
    for (; i + 4 <= e; i += 4) {
        a0 += X[(long)(i    ) * FEATN + t];
        a1 += X[(long)(i + 1) * FEATN + t];
        a2 += X[(long)(i + 2) * FEATN + t];
        a3 += X[(long)(i + 3) * FEATN + t];
    }
    for (; i < e; i++) a0 += X[(long)i * FEATN + t];
    outp[(long)g * POOLW + pool_off + t] = (a0 + a1) + (a2 + a3);
}

// ---------------- launch ------------------------------------------------------
extern "C" void kernel_launch(void* const* d_in, const int* in_sizes, int n_in,
                              void* d_out, int out_size)
{
    const float* x     = (const float*)d_in[0];
    const int*   ei    = (const int*)d_in[1];    // int32 (JAX x64 disabled)
    const int*   batch = (const int*)d_in[2];
    const float* W0    = (const float*)d_in[3];
    const float* b0    = (const float*)d_in[4];
    const float* W1    = (const float*)d_in[5];
    const float* b1    = (const float*)d_in[6];
    const float* W2    = (const float*)d_in[7];
    const float* b2    = (const float*)d_in[8];

    int N = in_sizes[0] / FEATN;     // 50000
    int E = in_sizes[1] / 2;         // 800000
    int pool_elems = NGRAPH * POOLW; // 49152

    float* out = (float*)d_out;
    float* x3  = out + pool_elems;

    int gemm_blocks  = (N + 127) / 128;
    long gat_threads = (long)N * 32;
    int gat_blocks   = (int)((gat_threads + 255) / 256);

    // prep (gemm1 in slot 4 = ncu's capture slot)
    zero_kernel<<<(N + 255) / 256, 256>>>(N);                 // 1
    count_kernel<<<(E + 255) / 256, 256>>>(ei + E, E);        // 2
    scan_kernel<<<1, SCAN_T>>>(N);                            // 3
    gemm_tf32_kernel<<<gemm_blocks, 512>>>(0, x, W0, N);      // 4  <- profiled
    fill_kernel<<<(E + 255) / 256, 256>>>(ei, E);             // 5
    gbound_kernel<<<(N + 255) / 256, 256>>>(batch, N);        // 6

    // layer 1 (gemm already issued above)
    gather_kernel<<<gat_blocks, 256>>>(b0, 1, nullptr, N);
    segpool_kernel<<<NGRAPH, 128>>>(1, nullptr, out, 0);

    // layer 2
    gemm_tf32_kernel<<<gemm_blocks, 512>>>(1, nullptr, W1, N);
    gather_kernel<<<gat_blocks, 256>>>(b1, 2, nullptr, N);
    segpool_kernel<<<NGRAPH, 128>>>(2, nullptr, out, 128);

    // layer 3
    gemm_tf32_kernel<<<gemm_blocks, 512>>>(2, nullptr, W2, N);
    gather_kernel<<<gat_blocks, 256>>>(b2, 3, x3, N);
    segpool_kernel<<<NGRAPH, 128>>>(3, x3, out, 256);
}